// round 16
// baseline (speedup 1.0000x reference)
#include <cuda_runtime.h>
#include <cuda_bf16.h>
#include <math.h>
#include <stdint.h>

#define BATCH 32768
#define KP_X 784   // exact: 49 chunks of 16
#define KP_H 400   // exact: 25 chunks of 16
#define NQME 2304  // Q[0,2000) | mu[2048,2148) | eig[2176,2276) | alogits[2280,2285)

// ---------------- scratch (__device__ globals; no cudaMalloc allowed) ------
__device__ __align__(256) __nv_bfloat16 g_xhi[BATCH * KP_X];
__device__ __align__(256) __nv_bfloat16 g_xlo[BATCH * KP_X];
__device__ __align__(256) __nv_bfloat16 g_h1hi[BATCH * KP_H];
__device__ __align__(256) __nv_bfloat16 g_h1lo[BATCH * KP_H];
__device__ __align__(256) __nv_bfloat16 g_h3hi[BATCH * KP_H];
__device__ __align__(256) __nv_bfloat16 g_h3lo[BATCH * KP_H];
__device__ __align__(256) __nv_bfloat16 g_B1hi[400 * KP_X];
__device__ __align__(256) __nv_bfloat16 g_B1lo[400 * KP_X];
__device__ __align__(256) __nv_bfloat16 g_BQMhi[NQME * KP_H];
__device__ __align__(256) __nv_bfloat16 g_BQMlo[NQME * KP_H];
__device__ __align__(256) float g_bqme[NQME];
__device__ __align__(256) __nv_bfloat16 g_B4hi[784 * KP_H];
__device__ __align__(256) __nv_bfloat16 g_B4lo[784 * KP_H];
__device__ __align__(256) float g_lg[BATCH * 5];

// ---------------- helpers --------------------------------------------------
__device__ __forceinline__ uint32_t smem_u32(const void* p) {
    uint32_t a;
    asm("{ .reg .u64 t; cvta.to.shared.u64 t, %1; cvt.u32.u64 %0, t; }"
        : "=r"(a) : "l"(p));
    return a;
}
__device__ __forceinline__ void split2(float v, __nv_bfloat16& hi, __nv_bfloat16& lo) {
    hi = __float2bfloat16(v);
    lo = __float2bfloat16(v - __bfloat162float(hi));
}
template <int ACT>
__device__ __forceinline__ float act_apply(float v) {
    if (ACT == 1) return fmaxf(v, 0.f);
    if (ACT == 2) return expf(v);
    if (ACT == 3) return 1.f / (1.f + expf(-v));
    return v;
}

#define CP_ASYNC16(dst, src, sz) \
    asm volatile("cp.async.cg.shared.global [%0], [%1], 16, %2;" \
                 :: "r"(dst), "l"(src), "r"(sz) : "memory")
#define CP_COMMIT() asm volatile("cp.async.commit_group;" ::: "memory")
template <int NW>
__device__ __forceinline__ void cp_wait() {
    asm volatile("cp.async.wait_group %0;" :: "n"(NW) : "memory");
}

__device__ __forceinline__ void ldsm4(uint32_t* r, uint32_t addr) {
    asm volatile("ldmatrix.sync.aligned.m8n8.x4.shared.b16 {%0,%1,%2,%3}, [%4];"
                 : "=r"(r[0]), "=r"(r[1]), "=r"(r[2]), "=r"(r[3]) : "r"(addr));
}
__device__ __forceinline__ void mma16816(float* d, const uint32_t* a, const uint32_t* b) {
    asm volatile(
        "mma.sync.aligned.m16n8k16.row.col.f32.bf16.bf16.f32 "
        "{%0,%1,%2,%3}, {%4,%5,%6,%7}, {%8,%9}, {%0,%1,%2,%3};"
        : "+f"(d[0]), "+f"(d[1]), "+f"(d[2]), "+f"(d[3])
        : "r"(a[0]), "r"(a[1]), "r"(a[2]), "r"(a[3]), "r"(b[0]), "r"(b[1]));
}
__device__ __forceinline__ uint32_t redux_max(uint32_t v) {
    uint32_t m;
    asm("redux.sync.max.u32 %0, %1, 0xffffffff;" : "=r"(m) : "r"(v));
    return m;
}

// BK=16: row stride 32B (2 x 16B chunks); conflict-free swizzle
__device__ __forceinline__ uint32_t swoff16(int row, int ch) {
    return ((uint32_t)row << 5) + ((uint32_t)(ch ^ ((row >> 2) & 1)) << 4);
}

// ---------------- fused prep (ONE launch) ----------------------------------
#define NB_X 25088
#define NB_W1 325          // 13 n-tiles x 25 k-tiles
#define NB_QME (72 * 13)   // 936
#define NB_BIAS 9
#define NB_W4 325          // 25 n-tiles x 13 k-tiles
#define NB_TOTAL (NB_X + NB_W1 + NB_QME + NB_BIAS + NB_W4)

__device__ __forceinline__ void wt_tile(const float* __restrict__ W,
                                        __nv_bfloat16* __restrict__ hi,
                                        __nv_bfloat16* __restrict__ lo,
                                        int K, int N, int Kp, int Np,
                                        int tileN, int tileK, float* s) {
    const int tx = threadIdx.x & 31, ty = threadIdx.x >> 5;
#pragma unroll
    for (int r = 0; r < 4; r++) {
        int kk = tileK + ty + r * 8, nn = tileN + tx;
        s[(ty + r * 8) * 33 + tx] = (kk < K && nn < N) ? W[(size_t)kk * N + nn] : 0.f;
    }
    __syncthreads();
#pragma unroll
    for (int r = 0; r < 4; r++) {
        int nn = tileN + ty + r * 8, kk = tileK + tx;
        if (nn < Np && kk < Kp) {
            __nv_bfloat16 h, l;
            split2(s[tx * 33 + ty + r * 8], h, l);
            hi[(size_t)nn * Kp + kk] = h;
            lo[(size_t)nn * Kp + kk] = l;
        }
    }
}

__device__ __forceinline__ float qme_src(const float* WQ, const float* Wmu,
                                         const float* We, const float* Wa,
                                         int k, int n) {
    if (k >= 400) return 0.f;
    if (n < 2000) return WQ[(size_t)k * 2000 + n];
    if (n >= 2048 && n < 2148) return Wmu[(size_t)k * 100 + (n - 2048)];
    if (n >= 2176 && n < 2276) return We[(size_t)k * 100 + (n - 2176)];
    if (n >= 2280 && n < 2285) return Wa[(size_t)k * 5 + (n - 2280)];
    return 0.f;
}

__global__ void __launch_bounds__(256)
mega_prep(const float* __restrict__ x, const float* __restrict__ W1,
          const float* __restrict__ WQ, const float* __restrict__ bQ,
          const float* __restrict__ Wmu, const float* __restrict__ bmu,
          const float* __restrict__ We, const float* __restrict__ be,
          const float* __restrict__ Wa, const float* __restrict__ ba,
          const float* __restrict__ W4,
          __nv_bfloat16* __restrict__ xhi, __nv_bfloat16* __restrict__ xlo,
          __nv_bfloat16* __restrict__ B1hi, __nv_bfloat16* __restrict__ B1lo,
          __nv_bfloat16* __restrict__ BQMhi, __nv_bfloat16* __restrict__ BQMlo,
          float* __restrict__ bqme,
          __nv_bfloat16* __restrict__ B4hi, __nv_bfloat16* __restrict__ B4lo) {
    __shared__ float s[32 * 33];
    int b = blockIdx.x;
    if (b < NB_X) {
        const int per_row = KP_X / 4;  // 196
        long i = (long)b * 256 + threadIdx.x;
        if (i < (long)BATCH * per_row) {
            int k = (int)(i % per_row) * 4;
            long r = i / per_row;
            float4 v = *(const float4*)(x + r * KP_X + k);
            __nv_bfloat16 h[4], l[4];
            split2(v.x, h[0], l[0]);
            split2(v.y, h[1], l[1]);
            split2(v.z, h[2], l[2]);
            split2(v.w, h[3], l[3]);
            *(uint2*)(xhi + r * KP_X + k) = *(uint2*)h;
            *(uint2*)(xlo + r * KP_X + k) = *(uint2*)l;
        }
        return;
    }
    b -= NB_X;
    if (b < NB_W1) {
        wt_tile(W1, B1hi, B1lo, 784, 400, KP_X, 400, (b % 13) * 32, (b / 13) * 32, s);
        return;
    }
    b -= NB_W1;
    if (b < NB_QME) {
        const int tileN = (b % 72) * 32, tileK = (b / 72) * 32;
        const int tx = threadIdx.x & 31, ty = threadIdx.x >> 5;
#pragma unroll
        for (int r = 0; r < 4; r++) {
            int kk = tileK + ty + r * 8, nn = tileN + tx;
            s[(ty + r * 8) * 33 + tx] = qme_src(WQ, Wmu, We, Wa, kk, nn);
        }
        __syncthreads();
#pragma unroll
        for (int r = 0; r < 4; r++) {
            int nn = tileN + ty + r * 8, kk = tileK + tx;
            if (kk < KP_H) {
                __nv_bfloat16 h, l;
                split2(s[tx * 33 + ty + r * 8], h, l);
                BQMhi[(size_t)nn * KP_H + kk] = h;
                BQMlo[(size_t)nn * KP_H + kk] = l;
            }
        }
        return;
    }
    b -= NB_QME;
    if (b < NB_BIAS) {
        int i = b * 256 + threadIdx.x;
        if (i < NQME) {
            float v = 0.f;
            if (i < 2000) v = bQ[i];
            else if (i >= 2048 && i < 2148) v = bmu[i - 2048];
            else if (i >= 2176 && i < 2276) v = be[i - 2176];
            else if (i >= 2280 && i < 2285) v = ba[i - 2280];
            bqme[i] = v;
        }
        return;
    }
    b -= NB_QME - NB_QME;  // no-op keeps structure clear
    b -= NB_BIAS;
    wt_tile(W4, B4hi, B4lo, 400, 784, KP_H, 784, (b % 25) * 32, (b / 25) * 32, s);
}

// ---------------- 3-term bf16 split GEMM on mma.sync -----------------------
// 256x128x16 CTA tile, 512 threads, 16 warps (8x2), warp tile 32x64,
// 4-stage cp.async. Per-warp inner loop identical to the 128x128 version;
// only the CTA shape changed (halves B re-read traffic through L2).
#define STAGES 4
#define STAGE_BYTES 24576     // Ahi 8K | Alo 8K | Bhi 4K | Blo 4K
#define GEMM_SMEM (STAGES * STAGE_BYTES)

__device__ __forceinline__ void qme_store(float* __restrict__ Q, float* __restrict__ mu,
                                          float* __restrict__ eig, float* __restrict__ lg,
                                          size_t row, int col, float v) {
    if (col < 2000) Q[row * 2000 + col] = expf(v);
    else if (col >= 2048 && col < 2148) mu[row * 100 + (col - 2048)] = v;
    else if (col >= 2176 && col < 2276) eig[row * 100 + (col - 2176)] = expf(v);
    else if (col >= 2280 && col < 2285) lg[row * 5 + (col - 2280)] = v;
}

template <int ACT, bool SPLIT_OUT>
__global__ void __launch_bounds__(512, 1)
mma_gemm(const __nv_bfloat16* __restrict__ Ahi, const __nv_bfloat16* __restrict__ Alo,
         const __nv_bfloat16* __restrict__ Bhi, const __nv_bfloat16* __restrict__ Blo,
         const float* __restrict__ bias, float* __restrict__ C, float* __restrict__ C2,
         float* __restrict__ C3, float* __restrict__ C4,
         __nv_bfloat16* __restrict__ outHi, __nv_bfloat16* __restrict__ outLo,
         int N, int Kp, int ldOut) {
    extern __shared__ char smem[];
    const uint32_t sbase = smem_u32(smem);
    const int tid = threadIdx.x, wid = tid >> 5, lane = tid & 31;
    const int wm = wid >> 1, wn = wid & 1;           // wm 0..7, wn 0..1
    const int rowBase = blockIdx.y * 256, colBase = blockIdx.x * 128;
    const int NC = Kp >> 4;

    float acc[2][8][4];
#pragma unroll
    for (int i = 0; i < 2; i++)
#pragma unroll
        for (int j = 0; j < 8; j++)
#pragma unroll
            for (int q = 0; q < 4; q++) acc[i][j][q] = 0.f;

    auto load_stage = [&](int c, int stg) {
        const int kBase = c << 4;
        const uint32_t sb = sbase + stg * STAGE_BYTES;
        const int row = tid >> 1, ch = tid & 1;       // row 0..255
        const uint32_t o = swoff16(row, ch);
        const int arow = rowBase + row;
        const size_t aoff = (size_t)arow * Kp + kBase + ch * 8;
        CP_ASYNC16(sb + o, Ahi + aoff, 16);
        CP_ASYNC16(sb + 8192 + o, Alo + aoff, 16);
        if (tid < 256) {
            int brow = colBase + row, bsz = 16;
            if (brow >= N) { brow = 0; bsz = 0; }
            const size_t boff = (size_t)brow * Kp + kBase + ch * 8;
            CP_ASYNC16(sb + 16384 + o, Bhi + boff, bsz);
            CP_ASYNC16(sb + 20480 + o, Blo + boff, bsz);
        }
    };

    load_stage(0, 0);
    CP_COMMIT();
    load_stage(1, 1);
    CP_COMMIT();
    load_stage(2, 2);
    CP_COMMIT();

    for (int c = 0; c < NC; c++) {
        cp_wait<STAGES - 2>();
        __syncthreads();
        if (c + STAGES - 1 < NC) {
            load_stage(c + STAGES - 1, (c + STAGES - 1) % STAGES);
            CP_COMMIT();
        }
        const uint32_t sb = sbase + (c % STAGES) * STAGE_BYTES;

        uint32_t ahi[2][4], alo[2][4];
#pragma unroll
        for (int mi = 0; mi < 2; mi++) {
            int row = wm * 32 + mi * 16 + (lane & 15);
            int ch = lane >> 4;
            uint32_t o = swoff16(row, ch);
            ldsm4(ahi[mi], sb + o);
            ldsm4(alo[mi], sb + 8192 + o);
        }
#pragma unroll
        for (int bi = 0; bi < 4; bi++) {
            int row = wn * 64 + bi * 16 + (lane & 7) + ((lane >> 4) << 3);
            int ch = (lane >> 3) & 1;
            uint32_t o = swoff16(row, ch);
            uint32_t bhi[4], blo[4];
            ldsm4(bhi, sb + 16384 + o);
            ldsm4(blo, sb + 20480 + o);
            mma16816(acc[0][2 * bi],     ahi[0], bhi);
            mma16816(acc[0][2 * bi + 1], ahi[0], bhi + 2);
            mma16816(acc[1][2 * bi],     ahi[1], bhi);
            mma16816(acc[1][2 * bi + 1], ahi[1], bhi + 2);
            mma16816(acc[0][2 * bi],     alo[0], bhi);
            mma16816(acc[0][2 * bi + 1], alo[0], bhi + 2);
            mma16816(acc[1][2 * bi],     alo[1], bhi);
            mma16816(acc[1][2 * bi + 1], alo[1], bhi + 2);
            mma16816(acc[0][2 * bi],     ahi[0], blo);
            mma16816(acc[0][2 * bi + 1], ahi[0], blo + 2);
            mma16816(acc[1][2 * bi],     ahi[1], blo);
            mma16816(acc[1][2 * bi + 1], ahi[1], blo + 2);
        }
    }

    // ---------------- epilogue ----------------
#pragma unroll
    for (int mi = 0; mi < 2; mi++) {
#pragma unroll
        for (int ni = 0; ni < 8; ni++) {
            const float* a4 = acc[mi][ni];
            const int r0 = rowBase + wm * 32 + mi * 16 + (lane >> 2);
            const int col = colBase + wn * 64 + ni * 8 + ((lane & 3) << 1);
            float b0 = (col < N) ? bias[col] : 0.f;
            float b1 = (col + 1 < N) ? bias[col + 1] : 0.f;
#pragma unroll
            for (int h = 0; h < 2; h++) {
                const size_t row = (size_t)(r0 + h * 8);
                if (ACT == 5) {  // fused Q | mu | eigen | a-logits
                    qme_store(C, C2, C3, C4, row, col, a4[2 * h + 0] + b0);
                    qme_store(C, C2, C3, C4, row, col + 1, a4[2 * h + 1] + b1);
                    continue;
                }
                const float v0 = act_apply<ACT>(a4[2 * h + 0] + b0);
                const float v1 = act_apply<ACT>(a4[2 * h + 1] + b1);
                if (SPLIT_OUT) {
                    if (col < N) {
                        __nv_bfloat16 hh, ll;
                        split2(v0, hh, ll);
                        outHi[row * ldOut + col] = hh;
                        outLo[row * ldOut + col] = ll;
                        if (col + 1 < N) {
                            split2(v1, hh, ll);
                            outHi[row * ldOut + col + 1] = hh;
                            outLo[row * ldOut + col + 1] = ll;
                        }
                    }
                } else {
                    if (col < N) C[row * ldOut + col] = v0;
                    if (col + 1 < N) C[row * ldOut + col + 1] = v1;
                }
            }
        }
    }
}

// ---------------- fused solve + h3 kernel (2 rows per warp) ----------------
__global__ void __launch_bounds__(256, 4)
solve_h3_kernel(const float* __restrict__ lg, const float* __restrict__ u,
                const float* __restrict__ eps,
                const float* __restrict__ outQ, const float* __restrict__ outMu,
                const float* __restrict__ outEig, float* __restrict__ outA,
                const float* __restrict__ W3, const float* __restrict__ b3,
                __nv_bfloat16* __restrict__ h3hi, __nv_bfloat16* __restrict__ h3lo) {
    __shared__ float Qs[8][420];       // stride-21 rows: conflict-free
    __shared__ float W3s[20 * 401];    // stride-401: conflict-free column reads
    __shared__ float b3s[400];
    const unsigned FULL = 0xffffffffu;
    const int w = threadIdx.x >> 5, lane = threadIdx.x & 31;

    // stage W3 (20x400) and b3
    for (int i = threadIdx.x; i < 20 * 400; i += 256) {
        int k = i / 400, c = i - k * 400;
        W3s[k * 401 + c] = W3[i];
    }
    for (int i = threadIdx.x; i < 400; i += 256) b3s[i] = b3[i];
    __syncthreads();

    for (int it = 0; it < 2; it++) {
        const int row = blockIdx.x * 16 + w * 2 + it;

        // --- softmax over 5 precomputed logits ---
        const float* lr = lg + (size_t)row * 5;
        float s0 = lr[0], s1 = lr[1], s2 = lr[2], s3 = lr[3], s4 = lr[4];
        float mx = fmaxf(fmaxf(fmaxf(s0, s1), fmaxf(s2, s3)), s4);
        float e0 = expf(s0 - mx), e1 = expf(s1 - mx), e2 = expf(s2 - mx),
              e3 = expf(s3 - mx), e4 = expf(s4 - mx);
        float inv = 1.f / (e0 + e1 + e2 + e3 + e4);
        float av[5] = {e0 * inv, e1 * inv, e2 * inv, e3 * inv, e4 * inv};
        if (lane == 0) {
            float* ar = outA + (size_t)row * 5;
            ar[0] = av[0]; ar[1] = av[1]; ar[2] = av[2]; ar[3] = av[3]; ar[4] = av[4];
        }

        float uu = u[row];
        int idx = 0;
        bool found = false;
        float c = 0.f;
#pragma unroll
        for (int j = 0; j < 5; j++) {
            c += av[j];
            if (!found && uu < c) { idx = j; found = true; }
        }

        const float* Qr = outQ + (size_t)row * 2000 + idx * 400;
        for (int k = lane; k < 400; k += 32) {
            int i = k / 20, j = k - i * 20;
            Qs[w][i * 21 + j] = Qr[k];
        }
        __syncwarp();

        float r[20];
        float rhs = 0.f, eig = 0.f, mui = 0.f;
        if (lane < 20) {
#pragma unroll
            for (int j = 0; j < 20; j++) r[j] = Qs[w][lane * 21 + j];
            rhs = eps[(size_t)row * 20 + lane];
            eig = outEig[(size_t)row * 100 + idx * 20 + lane];
            mui = outMu[(size_t)row * 100 + idx * 20 + lane];
        } else {
#pragma unroll
            for (int j = 0; j < 20; j++) r[j] = 0.f;
        }

        // --- pivoted LU without row swaps ---
        unsigned done = 0;
        int p[20];
#pragma unroll
        for (int k = 0; k < 20; k++) {
            bool active = (lane < 20) && !(done & (1u << lane));
            uint32_t key = active ? __float_as_uint(fabsf(r[k])) : 0u;
            uint32_t m = redux_max(key);
            unsigned msk = __ballot_sync(FULL, active && key == m);
            int pi = __ffs(msk) - 1;
            p[k] = pi;
            done |= (1u << pi);
            float akk = __shfl_sync(FULL, r[k], pi);
            float prhs = __shfl_sync(FULL, rhs, pi);
            bool elim = (lane < 20) && !(done & (1u << lane));
            float mlt = elim ? r[k] / akk : 0.f;
            rhs = fmaf(-mlt, prhs, rhs);
#pragma unroll
            for (int j = k + 1; j < 20; j++) {
                float pj = __shfl_sync(FULL, r[j], pi);
                r[j] = fmaf(-mlt, pj, r[j]);
            }
        }

        // --- back substitution in pivot order ---
        float y = 0.f;
#pragma unroll
        for (int k = 19; k >= 0; k--) {
            int pk = p[k];
            float num = __shfl_sync(FULL, rhs, pk);
            float akk = __shfl_sync(FULL, r[k], pk);
            float yk = num / akk;
            if (lane == k) y = yk;
            rhs = fmaf(-r[k], yk, rhs);
        }

        // --- z = Q (eigen .* y) + mu  (Q re-read from smem) ---
        float wv = eig * y;
        float zv = mui;
#pragma unroll
        for (int j = 0; j < 20; j++) {
            float wj = __shfl_sync(FULL, wv, j);
            zv = fmaf(Qs[w][lane * 21 + j], wj, zv);
        }
        __syncwarp();
        if (lane < 20) Qs[w][lane] = zv;   // stage z row (Q row dead)
        __syncwarp();

        // --- h3 = relu(z @ W3 + b3) -> bf16 hi/lo ---
        const size_t hbase = (size_t)row * KP_H;
        for (int c0 = lane; c0 < 400; c0 += 32) {
            float acc = b3s[c0];
#pragma unroll
            for (int k = 0; k < 20; k++)
                acc = fmaf(Qs[w][k], W3s[k * 401 + c0], acc);
            float v = fmaxf(acc, 0.f);
            __nv_bfloat16 h, l;
            split2(v, h, l);
            h3hi[hbase + c0] = h;
            h3lo[hbase + c0] = l;
        }
        __syncwarp();
    }
}

// ---------------- launch ---------------------------------------------------
extern "C" void kernel_launch(void* const* d_in, const int* in_sizes, int n_in,
                              void* d_out, int out_size) {
    const float* x   = (const float*)d_in[0];
    const float* u   = (const float*)d_in[1];
    const float* eps = (const float*)d_in[2];
    const float* W1  = (const float*)d_in[3];
    const float* b1  = (const float*)d_in[4];
    const float* Wmu = (const float*)d_in[5];
    const float* bmu = (const float*)d_in[6];
    const float* WQ  = (const float*)d_in[7];
    const float* bQ  = (const float*)d_in[8];
    const float* Wa  = (const float*)d_in[9];
    const float* ba  = (const float*)d_in[10];
    const float* We  = (const float*)d_in[11];
    const float* be  = (const float*)d_in[12];
    const float* W3  = (const float*)d_in[13];
    const float* b3  = (const float*)d_in[14];
    const float* W4  = (const float*)d_in[15];
    const float* b4  = (const float*)d_in[16];

    float* out = (float*)d_out;
    float* out_recon = out;
    float* out_mu    = out_recon + (size_t)BATCH * 784;
    float* out_Q     = out_mu    + (size_t)BATCH * 100;
    float* out_a     = out_Q     + (size_t)BATCH * 2000;
    float* out_eig   = out_a     + (size_t)BATCH * 5;

    __nv_bfloat16 *xhi, *xlo, *h1hi, *h1lo, *h3hi, *h3lo;
    __nv_bfloat16 *B1hi, *B1lo, *BQMhi, *BQMlo, *B4hi, *B4lo;
    float *bqme, *lgp;
    cudaGetSymbolAddress((void**)&xhi, g_xhi);
    cudaGetSymbolAddress((void**)&xlo, g_xlo);
    cudaGetSymbolAddress((void**)&h1hi, g_h1hi);
    cudaGetSymbolAddress((void**)&h1lo, g_h1lo);
    cudaGetSymbolAddress((void**)&h3hi, g_h3hi);
    cudaGetSymbolAddress((void**)&h3lo, g_h3lo);
    cudaGetSymbolAddress((void**)&B1hi, g_B1hi);
    cudaGetSymbolAddress((void**)&B1lo, g_B1lo);
    cudaGetSymbolAddress((void**)&BQMhi, g_BQMhi);
    cudaGetSymbolAddress((void**)&BQMlo, g_BQMlo);
    cudaGetSymbolAddress((void**)&bqme, g_bqme);
    cudaGetSymbolAddress((void**)&B4hi, g_B4hi);
    cudaGetSymbolAddress((void**)&B4lo, g_B4lo);
    cudaGetSymbolAddress((void**)&lgp, g_lg);

    cudaFuncSetAttribute(mma_gemm<1, true>,  cudaFuncAttributeMaxDynamicSharedMemorySize, GEMM_SMEM);
    cudaFuncSetAttribute(mma_gemm<5, false>, cudaFuncAttributeMaxDynamicSharedMemorySize, GEMM_SMEM);
    cudaFuncSetAttribute(mma_gemm<3, false>, cudaFuncAttributeMaxDynamicSharedMemorySize, GEMM_SMEM);

    // #1 all prep in ONE launch
    mega_prep<<<NB_TOTAL, 256>>>(x, W1, WQ, bQ, Wmu, bmu, We, be, Wa, ba, W4,
                                 xhi, xlo, B1hi, B1lo, BQMhi, BQMlo, bqme,
                                 B4hi, B4lo);
    // #2 h1 = relu(x@W1+b1) -> bf16 hi/lo
    mma_gemm<1, true><<<dim3(4, 128), 512, GEMM_SMEM>>>(
        xhi, xlo, B1hi, B1lo, b1, nullptr, nullptr, nullptr, nullptr,
        h1hi, h1lo, 400, KP_X, KP_H);
    // #3 fused Q | mu | eigen | a-logits GEMM (N=2304)
    mma_gemm<5, false><<<dim3(18, 128), 512, GEMM_SMEM>>>(
        h1hi, h1lo, BQMhi, BQMlo, bqme, out_Q, out_mu, out_eig, lgp,
        nullptr, nullptr, NQME, KP_H, 0);
    // #4 softmax / idx / LU solve / z / h3 (fused, 2 rows/warp)
    solve_h3_kernel<<<BATCH / 16, 256>>>(lgp, u, eps, out_Q, out_mu, out_eig,
                                         out_a, W3, b3, h3hi, h3lo);
    // #5 recon = sigmoid(h3@W4+b4)
    mma_gemm<3, false><<<dim3(7, 128), 512, GEMM_SMEM>>>(
        h3hi, h3lo, B4hi, B4lo, b4, out_recon, nullptr, nullptr, nullptr,
        nullptr, nullptr, 784, KP_H, 784);
}

// round 17
// speedup vs baseline: 1.0616x; 1.0616x over previous
#include <cuda_runtime.h>
#include <cuda_bf16.h>
#include <math.h>
#include <stdint.h>

#define BATCH 32768
#define KP_X 784   // exact: 49 chunks of 16
#define KP_H 400   // exact: 25 chunks of 16
#define NQME 2304  // Q[0,2000) | mu[2048,2148) | eig[2176,2276) | alogits[2280,2285)

// ---------------- scratch (__device__ globals; no cudaMalloc allowed) ------
__device__ __align__(256) __nv_bfloat16 g_xhi[BATCH * KP_X];
__device__ __align__(256) __nv_bfloat16 g_xlo[BATCH * KP_X];
__device__ __align__(256) __nv_bfloat16 g_h1hi[BATCH * KP_H];
__device__ __align__(256) __nv_bfloat16 g_h1lo[BATCH * KP_H];
__device__ __align__(256) __nv_bfloat16 g_h3hi[BATCH * KP_H];
__device__ __align__(256) __nv_bfloat16 g_h3lo[BATCH * KP_H];
__device__ __align__(256) __nv_bfloat16 g_B1hi[400 * KP_X];
__device__ __align__(256) __nv_bfloat16 g_B1lo[400 * KP_X];
__device__ __align__(256) __nv_bfloat16 g_BQMhi[NQME * KP_H];
__device__ __align__(256) __nv_bfloat16 g_BQMlo[NQME * KP_H];
__device__ __align__(256) float g_bqme[NQME];
__device__ __align__(256) __nv_bfloat16 g_B4hi[784 * KP_H];
__device__ __align__(256) __nv_bfloat16 g_B4lo[784 * KP_H];
__device__ __align__(256) float g_lg[BATCH * 5];

// ---------------- helpers --------------------------------------------------
__device__ __forceinline__ uint32_t smem_u32(const void* p) {
    uint32_t a;
    asm("{ .reg .u64 t; cvta.to.shared.u64 t, %1; cvt.u32.u64 %0, t; }"
        : "=r"(a) : "l"(p));
    return a;
}
__device__ __forceinline__ void split2(float v, __nv_bfloat16& hi, __nv_bfloat16& lo) {
    hi = __float2bfloat16(v);
    lo = __float2bfloat16(v - __bfloat162float(hi));
}
template <int ACT>
__device__ __forceinline__ float act_apply(float v) {
    if (ACT == 1) return fmaxf(v, 0.f);
    if (ACT == 2) return expf(v);
    if (ACT == 3) return 1.f / (1.f + expf(-v));
    return v;
}

#define CP_ASYNC16(dst, src, sz) \
    asm volatile("cp.async.cg.shared.global [%0], [%1], 16, %2;" \
                 :: "r"(dst), "l"(src), "r"(sz) : "memory")
#define CP_COMMIT() asm volatile("cp.async.commit_group;" ::: "memory")
template <int NW>
__device__ __forceinline__ void cp_wait() {
    asm volatile("cp.async.wait_group %0;" :: "n"(NW) : "memory");
}

__device__ __forceinline__ void ldsm4(uint32_t* r, uint32_t addr) {
    asm volatile("ldmatrix.sync.aligned.m8n8.x4.shared.b16 {%0,%1,%2,%3}, [%4];"
                 : "=r"(r[0]), "=r"(r[1]), "=r"(r[2]), "=r"(r[3]) : "r"(addr));
}
__device__ __forceinline__ void mma16816(float* d, const uint32_t* a, const uint32_t* b) {
    asm volatile(
        "mma.sync.aligned.m16n8k16.row.col.f32.bf16.bf16.f32 "
        "{%0,%1,%2,%3}, {%4,%5,%6,%7}, {%8,%9}, {%0,%1,%2,%3};"
        : "+f"(d[0]), "+f"(d[1]), "+f"(d[2]), "+f"(d[3])
        : "r"(a[0]), "r"(a[1]), "r"(a[2]), "r"(a[3]), "r"(b[0]), "r"(b[1]));
}
__device__ __forceinline__ uint32_t redux_max(uint32_t v) {
    uint32_t m;
    asm("redux.sync.max.u32 %0, %1, 0xffffffff;" : "=r"(m) : "r"(v));
    return m;
}

// BK=16: row stride 32B (2 x 16B chunks); conflict-free swizzle
__device__ __forceinline__ uint32_t swoff16(int row, int ch) {
    return ((uint32_t)row << 5) + ((uint32_t)(ch ^ ((row >> 2) & 1)) << 4);
}

// ---------------- fused prep (ONE launch) ----------------------------------
#define NB_X 25088
#define NB_W1 325          // 13 n-tiles x 25 k-tiles
#define NB_QME (72 * 13)   // 936
#define NB_BIAS 9
#define NB_W4 325          // 25 n-tiles x 13 k-tiles
#define NB_TOTAL (NB_X + NB_W1 + NB_QME + NB_BIAS + NB_W4)

__device__ __forceinline__ void wt_tile(const float* __restrict__ W,
                                        __nv_bfloat16* __restrict__ hi,
                                        __nv_bfloat16* __restrict__ lo,
                                        int K, int N, int Kp, int Np,
                                        int tileN, int tileK, float* s) {
    const int tx = threadIdx.x & 31, ty = threadIdx.x >> 5;
#pragma unroll
    for (int r = 0; r < 4; r++) {
        int kk = tileK + ty + r * 8, nn = tileN + tx;
        s[(ty + r * 8) * 33 + tx] = (kk < K && nn < N) ? W[(size_t)kk * N + nn] : 0.f;
    }
    __syncthreads();
#pragma unroll
    for (int r = 0; r < 4; r++) {
        int nn = tileN + ty + r * 8, kk = tileK + tx;
        if (nn < Np && kk < Kp) {
            __nv_bfloat16 h, l;
            split2(s[tx * 33 + ty + r * 8], h, l);
            hi[(size_t)nn * Kp + kk] = h;
            lo[(size_t)nn * Kp + kk] = l;
        }
    }
}

__device__ __forceinline__ float qme_src(const float* WQ, const float* Wmu,
                                         const float* We, const float* Wa,
                                         int k, int n) {
    if (k >= 400) return 0.f;
    if (n < 2000) return WQ[(size_t)k * 2000 + n];
    if (n >= 2048 && n < 2148) return Wmu[(size_t)k * 100 + (n - 2048)];
    if (n >= 2176 && n < 2276) return We[(size_t)k * 100 + (n - 2176)];
    if (n >= 2280 && n < 2285) return Wa[(size_t)k * 5 + (n - 2280)];
    return 0.f;
}

__global__ void __launch_bounds__(256)
mega_prep(const float* __restrict__ x, const float* __restrict__ W1,
          const float* __restrict__ WQ, const float* __restrict__ bQ,
          const float* __restrict__ Wmu, const float* __restrict__ bmu,
          const float* __restrict__ We, const float* __restrict__ be,
          const float* __restrict__ Wa, const float* __restrict__ ba,
          const float* __restrict__ W4,
          __nv_bfloat16* __restrict__ xhi, __nv_bfloat16* __restrict__ xlo,
          __nv_bfloat16* __restrict__ B1hi, __nv_bfloat16* __restrict__ B1lo,
          __nv_bfloat16* __restrict__ BQMhi, __nv_bfloat16* __restrict__ BQMlo,
          float* __restrict__ bqme,
          __nv_bfloat16* __restrict__ B4hi, __nv_bfloat16* __restrict__ B4lo) {
    __shared__ float s[32 * 33];
    int b = blockIdx.x;
    if (b < NB_X) {
        const int per_row = KP_X / 4;  // 196
        long i = (long)b * 256 + threadIdx.x;
        if (i < (long)BATCH * per_row) {
            int k = (int)(i % per_row) * 4;
            long r = i / per_row;
            float4 v = *(const float4*)(x + r * KP_X + k);
            __nv_bfloat16 h[4], l[4];
            split2(v.x, h[0], l[0]);
            split2(v.y, h[1], l[1]);
            split2(v.z, h[2], l[2]);
            split2(v.w, h[3], l[3]);
            *(uint2*)(xhi + r * KP_X + k) = *(uint2*)h;
            *(uint2*)(xlo + r * KP_X + k) = *(uint2*)l;
        }
        return;
    }
    b -= NB_X;
    if (b < NB_W1) {
        wt_tile(W1, B1hi, B1lo, 784, 400, KP_X, 400, (b % 13) * 32, (b / 13) * 32, s);
        return;
    }
    b -= NB_W1;
    if (b < NB_QME) {
        const int tileN = (b % 72) * 32, tileK = (b / 72) * 32;
        const int tx = threadIdx.x & 31, ty = threadIdx.x >> 5;
#pragma unroll
        for (int r = 0; r < 4; r++) {
            int kk = tileK + ty + r * 8, nn = tileN + tx;
            s[(ty + r * 8) * 33 + tx] = qme_src(WQ, Wmu, We, Wa, kk, nn);
        }
        __syncthreads();
#pragma unroll
        for (int r = 0; r < 4; r++) {
            int nn = tileN + ty + r * 8, kk = tileK + tx;
            if (kk < KP_H) {
                __nv_bfloat16 h, l;
                split2(s[tx * 33 + ty + r * 8], h, l);
                BQMhi[(size_t)nn * KP_H + kk] = h;
                BQMlo[(size_t)nn * KP_H + kk] = l;
            }
        }
        return;
    }
    b -= NB_QME;
    if (b < NB_BIAS) {
        int i = b * 256 + threadIdx.x;
        if (i < NQME) {
            float v = 0.f;
            if (i < 2000) v = bQ[i];
            else if (i >= 2048 && i < 2148) v = bmu[i - 2048];
            else if (i >= 2176 && i < 2276) v = be[i - 2176];
            else if (i >= 2280 && i < 2285) v = ba[i - 2280];
            bqme[i] = v;
        }
        return;
    }
    b -= NB_BIAS;
    wt_tile(W4, B4hi, B4lo, 400, 784, KP_H, 784, (b % 25) * 32, (b / 25) * 32, s);
}

// ---------------- 3-term bf16 split GEMM on mma.sync (R9/R15 config) -------
// 128x128x16 CTA tile, 256 threads, 8 warps (4x2), warp tile 32x64,
// 4-stage cp.async, 2 CTAs/SM.
#define STAGES 4
#define STAGE_BYTES 16384
#define GEMM_SMEM (STAGES * STAGE_BYTES)

__device__ __forceinline__ void qme_store(float* __restrict__ Q, float* __restrict__ mu,
                                          float* __restrict__ eig, float* __restrict__ lg,
                                          size_t row, int col, float v) {
    if (col < 2000) Q[row * 2000 + col] = expf(v);
    else if (col >= 2048 && col < 2148) mu[row * 100 + (col - 2048)] = v;
    else if (col >= 2176 && col < 2276) eig[row * 100 + (col - 2176)] = expf(v);
    else if (col >= 2280 && col < 2285) lg[row * 5 + (col - 2280)] = v;
}

template <int ACT, bool SPLIT_OUT>
__global__ void __launch_bounds__(256, 2)
mma_gemm(const __nv_bfloat16* __restrict__ Ahi, const __nv_bfloat16* __restrict__ Alo,
         const __nv_bfloat16* __restrict__ Bhi, const __nv_bfloat16* __restrict__ Blo,
         const float* __restrict__ bias, float* __restrict__ C, float* __restrict__ C2,
         float* __restrict__ C3, float* __restrict__ C4,
         __nv_bfloat16* __restrict__ outHi, __nv_bfloat16* __restrict__ outLo,
         int N, int Kp, int ldOut) {
    extern __shared__ char smem[];
    const uint32_t sbase = smem_u32(smem);
    const int tid = threadIdx.x, wid = tid >> 5, lane = tid & 31;
    const int wm = wid >> 1, wn = wid & 1;
    const int rowBase = blockIdx.y * 128, colBase = blockIdx.x * 128;
    const int NC = Kp >> 4;

    float acc[2][8][4];
#pragma unroll
    for (int i = 0; i < 2; i++)
#pragma unroll
        for (int j = 0; j < 8; j++)
#pragma unroll
            for (int q = 0; q < 4; q++) acc[i][j][q] = 0.f;

    auto load_stage = [&](int c, int stg) {
        const int kBase = c << 4;
        const uint32_t sb = sbase + stg * STAGE_BYTES;
        const int row = tid >> 1, ch = tid & 1;
        const uint32_t o = swoff16(row, ch);
        const int arow = rowBase + row;
        int brow = colBase + row, bsz = 16;
        if (brow >= N) { brow = 0; bsz = 0; }
        const size_t aoff = (size_t)arow * Kp + kBase + ch * 8;
        const size_t boff = (size_t)brow * Kp + kBase + ch * 8;
        CP_ASYNC16(sb + o, Ahi + aoff, 16);
        CP_ASYNC16(sb + 4096 + o, Alo + aoff, 16);
        CP_ASYNC16(sb + 8192 + o, Bhi + boff, bsz);
        CP_ASYNC16(sb + 12288 + o, Blo + boff, bsz);
    };

    load_stage(0, 0);
    CP_COMMIT();
    load_stage(1, 1);
    CP_COMMIT();
    load_stage(2, 2);
    CP_COMMIT();

    for (int c = 0; c < NC; c++) {
        cp_wait<STAGES - 2>();
        __syncthreads();
        if (c + STAGES - 1 < NC) {
            load_stage(c + STAGES - 1, (c + STAGES - 1) % STAGES);
            CP_COMMIT();
        }
        const uint32_t sb = sbase + (c % STAGES) * STAGE_BYTES;

        uint32_t ahi[2][4], alo[2][4];
#pragma unroll
        for (int mi = 0; mi < 2; mi++) {
            int row = wm * 32 + mi * 16 + (lane & 15);
            int ch = lane >> 4;
            uint32_t o = swoff16(row, ch);
            ldsm4(ahi[mi], sb + o);
            ldsm4(alo[mi], sb + 4096 + o);
        }
#pragma unroll
        for (int bi = 0; bi < 4; bi++) {
            int row = wn * 64 + bi * 16 + (lane & 7) + ((lane >> 4) << 3);
            int ch = (lane >> 3) & 1;
            uint32_t o = swoff16(row, ch);
            uint32_t bhi[4], blo[4];
            ldsm4(bhi, sb + 8192 + o);
            ldsm4(blo, sb + 12288 + o);
            mma16816(acc[0][2 * bi],     ahi[0], bhi);
            mma16816(acc[0][2 * bi + 1], ahi[0], bhi + 2);
            mma16816(acc[1][2 * bi],     ahi[1], bhi);
            mma16816(acc[1][2 * bi + 1], ahi[1], bhi + 2);
            mma16816(acc[0][2 * bi],     alo[0], bhi);
            mma16816(acc[0][2 * bi + 1], alo[0], bhi + 2);
            mma16816(acc[1][2 * bi],     alo[1], bhi);
            mma16816(acc[1][2 * bi + 1], alo[1], bhi + 2);
            mma16816(acc[0][2 * bi],     ahi[0], blo);
            mma16816(acc[0][2 * bi + 1], ahi[0], blo + 2);
            mma16816(acc[1][2 * bi],     ahi[1], blo);
            mma16816(acc[1][2 * bi + 1], ahi[1], blo + 2);
        }
    }

    // ---------------- epilogue ----------------
#pragma unroll
    for (int mi = 0; mi < 2; mi++) {
#pragma unroll
        for (int ni = 0; ni < 8; ni++) {
            const float* a4 = acc[mi][ni];
            const int r0 = rowBase + wm * 32 + mi * 16 + (lane >> 2);
            const int col = colBase + wn * 64 + ni * 8 + ((lane & 3) << 1);
            float b0 = (col < N) ? bias[col] : 0.f;
            float b1 = (col + 1 < N) ? bias[col + 1] : 0.f;
#pragma unroll
            for (int h = 0; h < 2; h++) {
                const size_t row = (size_t)(r0 + h * 8);
                if (ACT == 5) {  // fused Q | mu | eigen | a-logits
                    qme_store(C, C2, C3, C4, row, col, a4[2 * h + 0] + b0);
                    qme_store(C, C2, C3, C4, row, col + 1, a4[2 * h + 1] + b1);
                    continue;
                }
                const float v0 = act_apply<ACT>(a4[2 * h + 0] + b0);
                const float v1 = act_apply<ACT>(a4[2 * h + 1] + b1);
                if (SPLIT_OUT) {
                    if (col < N) {
                        __nv_bfloat16 hh, ll;
                        split2(v0, hh, ll);
                        outHi[row * ldOut + col] = hh;
                        outLo[row * ldOut + col] = ll;
                        if (col + 1 < N) {
                            split2(v1, hh, ll);
                            outHi[row * ldOut + col + 1] = hh;
                            outLo[row * ldOut + col + 1] = ll;
                        }
                    }
                } else {
                    if (col < N) C[row * ldOut + col] = v0;
                    if (col + 1 < N) C[row * ldOut + col + 1] = v1;
                }
            }
        }
    }
}

// ---------------- fused solve + h3 kernel (2 rows per warp, R16 version) ---
__global__ void __launch_bounds__(256, 4)
solve_h3_kernel(const float* __restrict__ lg, const float* __restrict__ u,
                const float* __restrict__ eps,
                const float* __restrict__ outQ, const float* __restrict__ outMu,
                const float* __restrict__ outEig, float* __restrict__ outA,
                const float* __restrict__ W3, const float* __restrict__ b3,
                __nv_bfloat16* __restrict__ h3hi, __nv_bfloat16* __restrict__ h3lo) {
    __shared__ float Qs[8][420];       // stride-21 rows: conflict-free
    __shared__ float W3s[20 * 401];    // stride-401: conflict-free column reads
    __shared__ float b3s[400];
    const unsigned FULL = 0xffffffffu;
    const int w = threadIdx.x >> 5, lane = threadIdx.x & 31;

    // stage W3 (20x400) and b3
    for (int i = threadIdx.x; i < 20 * 400; i += 256) {
        int k = i / 400, c = i - k * 400;
        W3s[k * 401 + c] = W3[i];
    }
    for (int i = threadIdx.x; i < 400; i += 256) b3s[i] = b3[i];
    __syncthreads();

    for (int it = 0; it < 2; it++) {
        const int row = blockIdx.x * 16 + w * 2 + it;

        // --- softmax over 5 precomputed logits ---
        const float* lr = lg + (size_t)row * 5;
        float s0 = lr[0], s1 = lr[1], s2 = lr[2], s3 = lr[3], s4 = lr[4];
        float mx = fmaxf(fmaxf(fmaxf(s0, s1), fmaxf(s2, s3)), s4);
        float e0 = expf(s0 - mx), e1 = expf(s1 - mx), e2 = expf(s2 - mx),
              e3 = expf(s3 - mx), e4 = expf(s4 - mx);
        float inv = 1.f / (e0 + e1 + e2 + e3 + e4);
        float av[5] = {e0 * inv, e1 * inv, e2 * inv, e3 * inv, e4 * inv};
        if (lane == 0) {
            float* ar = outA + (size_t)row * 5;
            ar[0] = av[0]; ar[1] = av[1]; ar[2] = av[2]; ar[3] = av[3]; ar[4] = av[4];
        }

        float uu = u[row];
        int idx = 0;
        bool found = false;
        float c = 0.f;
#pragma unroll
        for (int j = 0; j < 5; j++) {
            c += av[j];
            if (!found && uu < c) { idx = j; found = true; }
        }

        const float* Qr = outQ + (size_t)row * 2000 + idx * 400;
        for (int k = lane; k < 400; k += 32) {
            int i = k / 20, j = k - i * 20;
            Qs[w][i * 21 + j] = Qr[k];
        }
        __syncwarp();

        float r[20];
        float rhs = 0.f, eig = 0.f, mui = 0.f;
        if (lane < 20) {
#pragma unroll
            for (int j = 0; j < 20; j++) r[j] = Qs[w][lane * 21 + j];
            rhs = eps[(size_t)row * 20 + lane];
            eig = outEig[(size_t)row * 100 + idx * 20 + lane];
            mui = outMu[(size_t)row * 100 + idx * 20 + lane];
        } else {
#pragma unroll
            for (int j = 0; j < 20; j++) r[j] = 0.f;
        }

        // --- pivoted LU without row swaps ---
        unsigned done = 0;
        int p[20];
#pragma unroll
        for (int k = 0; k < 20; k++) {
            bool active = (lane < 20) && !(done & (1u << lane));
            uint32_t key = active ? __float_as_uint(fabsf(r[k])) : 0u;
            uint32_t m = redux_max(key);
            unsigned msk = __ballot_sync(FULL, active && key == m);
            int pi = __ffs(msk) - 1;
            p[k] = pi;
            done |= (1u << pi);
            float akk = __shfl_sync(FULL, r[k], pi);
            float prhs = __shfl_sync(FULL, rhs, pi);
            bool elim = (lane < 20) && !(done & (1u << lane));
            float mlt = elim ? r[k] / akk : 0.f;
            rhs = fmaf(-mlt, prhs, rhs);
#pragma unroll
            for (int j = k + 1; j < 20; j++) {
                float pj = __shfl_sync(FULL, r[j], pi);
                r[j] = fmaf(-mlt, pj, r[j]);
            }
        }

        // --- back substitution in pivot order ---
        float y = 0.f;
#pragma unroll
        for (int k = 19; k >= 0; k--) {
            int pk = p[k];
            float num = __shfl_sync(FULL, rhs, pk);
            float akk = __shfl_sync(FULL, r[k], pk);
            float yk = num / akk;
            if (lane == k) y = yk;
            rhs = fmaf(-r[k], yk, rhs);
        }

        // --- z = Q (eigen .* y) + mu  (Q re-read from smem) ---
        float wv = eig * y;
        float zv = mui;
#pragma unroll
        for (int j = 0; j < 20; j++) {
            float wj = __shfl_sync(FULL, wv, j);
            zv = fmaf(Qs[w][lane * 21 + j], wj, zv);
        }
        __syncwarp();
        if (lane < 20) Qs[w][lane] = zv;   // stage z row (Q row dead)
        __syncwarp();

        // --- h3 = relu(z @ W3 + b3) -> bf16 hi/lo ---
        const size_t hbase = (size_t)row * KP_H;
        for (int c0 = lane; c0 < 400; c0 += 32) {
            float acc = b3s[c0];
#pragma unroll
            for (int k = 0; k < 20; k++)
                acc = fmaf(Qs[w][k], W3s[k * 401 + c0], acc);
            float v = fmaxf(acc, 0.f);
            __nv_bfloat16 h, l;
            split2(v, h, l);
            h3hi[hbase + c0] = h;
            h3lo[hbase + c0] = l;
        }
        __syncwarp();
    }
}

// ---------------- launch ---------------------------------------------------
extern "C" void kernel_launch(void* const* d_in, const int* in_sizes, int n_in,
                              void* d_out, int out_size) {
    const float* x   = (const float*)d_in[0];
    const float* u   = (const float*)d_in[1];
    const float* eps = (const float*)d_in[2];
    const float* W1  = (const float*)d_in[3];
    const float* b1  = (const float*)d_in[4];
    const float* Wmu = (const float*)d_in[5];
    const float* bmu = (const float*)d_in[6];
    const float* WQ  = (const float*)d_in[7];
    const float* bQ  = (const float*)d_in[8];
    const float* Wa  = (const float*)d_in[9];
    const float* ba  = (const float*)d_in[10];
    const float* We  = (const float*)d_in[11];
    const float* be  = (const float*)d_in[12];
    const float* W3  = (const float*)d_in[13];
    const float* b3  = (const float*)d_in[14];
    const float* W4  = (const float*)d_in[15];
    const float* b4  = (const float*)d_in[16];

    float* out = (float*)d_out;
    float* out_recon = out;
    float* out_mu    = out_recon + (size_t)BATCH * 784;
    float* out_Q     = out_mu    + (size_t)BATCH * 100;
    float* out_a     = out_Q     + (size_t)BATCH * 2000;
    float* out_eig   = out_a     + (size_t)BATCH * 5;

    __nv_bfloat16 *xhi, *xlo, *h1hi, *h1lo, *h3hi, *h3lo;
    __nv_bfloat16 *B1hi, *B1lo, *BQMhi, *BQMlo, *B4hi, *B4lo;
    float *bqme, *lgp;
    cudaGetSymbolAddress((void**)&xhi, g_xhi);
    cudaGetSymbolAddress((void**)&xlo, g_xlo);
    cudaGetSymbolAddress((void**)&h1hi, g_h1hi);
    cudaGetSymbolAddress((void**)&h1lo, g_h1lo);
    cudaGetSymbolAddress((void**)&h3hi, g_h3hi);
    cudaGetSymbolAddress((void**)&h3lo, g_h3lo);
    cudaGetSymbolAddress((void**)&B1hi, g_B1hi);
    cudaGetSymbolAddress((void**)&B1lo, g_B1lo);
    cudaGetSymbolAddress((void**)&BQMhi, g_BQMhi);
    cudaGetSymbolAddress((void**)&BQMlo, g_BQMlo);
    cudaGetSymbolAddress((void**)&bqme, g_bqme);
    cudaGetSymbolAddress((void**)&B4hi, g_B4hi);
    cudaGetSymbolAddress((void**)&B4lo, g_B4lo);
    cudaGetSymbolAddress((void**)&lgp, g_lg);

    cudaFuncSetAttribute(mma_gemm<1, true>,  cudaFuncAttributeMaxDynamicSharedMemorySize, GEMM_SMEM);
    cudaFuncSetAttribute(mma_gemm<5, false>, cudaFuncAttributeMaxDynamicSharedMemorySize, GEMM_SMEM);
    cudaFuncSetAttribute(mma_gemm<3, false>, cudaFuncAttributeMaxDynamicSharedMemorySize, GEMM_SMEM);

    // #1 all prep in ONE launch
    mega_prep<<<NB_TOTAL, 256>>>(x, W1, WQ, bQ, Wmu, bmu, We, be, Wa, ba, W4,
                                 xhi, xlo, B1hi, B1lo, BQMhi, BQMlo, bqme,
                                 B4hi, B4lo);
    // #2 h1 = relu(x@W1+b1) -> bf16 hi/lo
    mma_gemm<1, true><<<dim3(4, 256), 256, GEMM_SMEM>>>(
        xhi, xlo, B1hi, B1lo, b1, nullptr, nullptr, nullptr, nullptr,
        h1hi, h1lo, 400, KP_X, KP_H);
    // #3 fused Q | mu | eigen | a-logits GEMM (N=2304)
    mma_gemm<5, false><<<dim3(18, 256), 256, GEMM_SMEM>>>(
        h1hi, h1lo, BQMhi, BQMlo, bqme, out_Q, out_mu, out_eig, lgp,
        nullptr, nullptr, NQME, KP_H, 0);
    // #4 softmax / idx / LU solve / z / h3 (fused, 2 rows/warp)
    solve_h3_kernel<<<BATCH / 16, 256>>>(lgp, u, eps, out_Q, out_mu, out_eig,
                                         out_a, W3, b3, h3hi, h3lo);
    // #5 recon = sigmoid(h3@W4+b4)
    mma_gemm<3, false><<<dim3(7, 256), 256, GEMM_SMEM>>>(
        h3hi, h3lo, B4hi, B4lo, b4, out_recon, nullptr, nullptr, nullptr,
        nullptr, nullptr, 784, KP_H, 784);
}